// round 4
// baseline (speedup 1.0000x reference)
#include <cuda_runtime.h>
#include <math.h>
#include <stdint.h>

#define B_   8
#define LQ_  2048
#define LK_  2048
#define HID_ 1024

// smem strides (floats): k-major tiles [row][k] stride 20; n-major [k][n] stride 264.
#define SK 20
#define SN 264

__device__ __forceinline__ unsigned f2tf(float x) {
    unsigned u;
    asm("cvt.rna.tf32.f32 %0, %1;" : "=r"(u) : "f"(x));
    return u;
}

__device__ __forceinline__ void mma_tf32(float* d, const unsigned* a, const unsigned* b) {
    asm volatile(
        "mma.sync.aligned.m16n8k8.row.col.f32.tf32.tf32.f32 "
        "{%0,%1,%2,%3}, {%4,%5,%6,%7}, {%8,%9}, {%0,%1,%2,%3};\n"
        : "+f"(d[0]), "+f"(d[1]), "+f"(d[2]), "+f"(d[3])
        : "r"(a[0]), "r"(a[1]), "r"(a[2]), "r"(a[3]),
          "r"(b[0]), "r"(b[1]));
}

// ---------------------------------------------------------------------------
// Kernel 1: P = exp( (Q.K^T / 32) * mask )   (unnormalized; k2 normalizes)
// CTA tile 128(M) x 256(N), BK=16, 256 threads = 8 warps (2 M x 4 N),
// warp tile 64x64. Double-buffered dynamic smem.
// smem floats: A0[2560] A1[2560] B0[5120] B1[5120]  (A:128xSK, B:256xSK)
// ---------------------------------------------------------------------------
__global__ __launch_bounds__(256, 1)
void k1_qk_exp(const float* __restrict__ Q, const float* __restrict__ Kf,
               const float* __restrict__ mask, float* __restrict__ P)
{
    extern __shared__ unsigned sm[];
    unsigned* sA[2] = { sm,            sm + 128 * SK };
    unsigned* sB[2] = { sm + 2 * 128 * SK, sm + 2 * 128 * SK + 256 * SK };

    const int b  = blockIdx.z;
    const int m0 = blockIdx.y * 128;
    const int n0 = blockIdx.x * 256;

    const float* Qb = Q  + (size_t)b * LQ_ * HID_;
    const float* Kb = Kf + (size_t)b * LK_ * HID_;

    const int tid  = threadIdx.x;
    const int wid  = tid >> 5;
    const int lane = tid & 31;
    const int qid  = lane >> 2;        // 0..7
    const int rid  = lane & 3;         // 0..3
    const int wm   = (wid & 1) * 64;   // warp M offset (2)
    const int wn   = (wid >> 1) * 64;  // warp N offset (4)

    // loaders: slot -> row = slot>>2, kq = (slot&3)*4
    const int lrow = tid >> 2;
    const int lkq  = (tid & 3) << 2;

    float acc[4][8][4];
#pragma unroll
    for (int i = 0; i < 4; i++)
#pragma unroll
        for (int j = 0; j < 8; j++)
#pragma unroll
            for (int c = 0; c < 4; c++) acc[i][j][c] = 0.0f;

    // prologue: stage 0 into buffer 0
    {
#pragma unroll
        for (int j = 0; j < 2; j++) {           // A: 128 rows
            const int row = lrow + j * 64;
            float4 v = *(const float4*)(Qb + (size_t)(m0 + row) * HID_ + lkq);
            *(uint4*)&sA[0][row * SK + lkq] =
                make_uint4(f2tf(v.x), f2tf(v.y), f2tf(v.z), f2tf(v.w));
        }
#pragma unroll
        for (int j = 0; j < 4; j++) {           // B: 256 rows
            const int row = lrow + j * 64;
            float4 v = *(const float4*)(Kb + (size_t)(n0 + row) * HID_ + lkq);
            *(uint4*)&sB[0][row * SK + lkq] =
                make_uint4(f2tf(v.x), f2tf(v.y), f2tf(v.z), f2tf(v.w));
        }
    }

    const int NIT = HID_ / 16;
    for (int it = 0; it < NIT; it++) {
        __syncthreads();
        const int cur = it & 1;
        const bool more = (it + 1) < NIT;

        float4 pa[2], pb[4];
        if (more) {
            const int kk = (it + 1) * 16;
#pragma unroll
            for (int j = 0; j < 2; j++)
                pa[j] = *(const float4*)(Qb + (size_t)(m0 + lrow + j * 64) * HID_ + kk + lkq);
#pragma unroll
            for (int j = 0; j < 4; j++)
                pb[j] = *(const float4*)(Kb + (size_t)(n0 + lrow + j * 64) * HID_ + kk + lkq);
        }

#pragma unroll
        for (int ks = 0; ks < 16; ks += 8) {
            unsigned af[4][4];
#pragma unroll
            for (int mt = 0; mt < 4; mt++) {
                const int r = wm + mt * 16 + qid;
                af[mt][0] = sA[cur][r * SK + ks + rid];
                af[mt][1] = sA[cur][(r + 8) * SK + ks + rid];
                af[mt][2] = sA[cur][r * SK + ks + 4 + rid];
                af[mt][3] = sA[cur][(r + 8) * SK + ks + 4 + rid];
            }
            unsigned bf[8][2];
#pragma unroll
            for (int nt = 0; nt < 8; nt++) {
                const int c = wn + nt * 8 + qid;
                bf[nt][0] = sB[cur][c * SK + ks + rid];
                bf[nt][1] = sB[cur][c * SK + ks + 4 + rid];
            }
#pragma unroll
            for (int mt = 0; mt < 4; mt++)
#pragma unroll
                for (int nt = 0; nt < 8; nt++)
                    mma_tf32(acc[mt][nt], af[mt], bf[nt]);
        }

        if (more) {
            const int nxt = cur ^ 1;
#pragma unroll
            for (int j = 0; j < 2; j++) {
                const int row = lrow + j * 64;
                *(uint4*)&sA[nxt][row * SK + lkq] =
                    make_uint4(f2tf(pa[j].x), f2tf(pa[j].y), f2tf(pa[j].z), f2tf(pa[j].w));
            }
#pragma unroll
            for (int j = 0; j < 4; j++) {
                const int row = lrow + j * 64;
                *(uint4*)&sB[nxt][row * SK + lkq] =
                    make_uint4(f2tf(pb[j].x), f2tf(pb[j].y), f2tf(pb[j].z), f2tf(pb[j].w));
            }
        }
    }

    // epilogue: scale, mask-multiply, exp, store
    const float s = 0.03125f;
#pragma unroll
    for (int mt = 0; mt < 4; mt++) {
#pragma unroll
        for (int nt = 0; nt < 8; nt++) {
            const int r = m0 + wm + mt * 16 + qid;
            const int c = n0 + wn + nt * 8 + 2 * rid;
            const size_t i0 = ((size_t)b * LQ_ + r) * LK_ + c;
            const size_t i1 = ((size_t)b * LQ_ + r + 8) * LK_ + c;
            float2 ma = *(const float2*)(mask + i0);
            float2 mb = *(const float2*)(mask + i1);
            float2 o0, o1;
            o0.x = __expf(acc[mt][nt][0] * s * ma.x);
            o0.y = __expf(acc[mt][nt][1] * s * ma.y);
            o1.x = __expf(acc[mt][nt][2] * s * mb.x);
            o1.y = __expf(acc[mt][nt][3] * s * mb.y);
            *(float2*)(P + i0) = o0;
            *(float2*)(P + i1) = o1;
        }
    }
}

// ---------------------------------------------------------------------------
// Kernel 2: per-row normalization
// ---------------------------------------------------------------------------
__global__ __launch_bounds__(256)
void k2_norm(float* __restrict__ P)
{
    __shared__ float red[256];
    float* prow = P + (size_t)blockIdx.x * LK_;
    const int tid = threadIdx.x;

    float4 v0 = ((const float4*)prow)[tid];
    float4 v1 = ((const float4*)prow)[tid + 256];
    float s = v0.x + v0.y + v0.z + v0.w + v1.x + v1.y + v1.z + v1.w;
    red[tid] = s;
    __syncthreads();
#pragma unroll
    for (int off = 128; off > 0; off >>= 1) {
        if (tid < off) red[tid] += red[tid + off];
        __syncthreads();
    }
    const float inv = 1.0f / red[0];
    v0.x *= inv; v0.y *= inv; v0.z *= inv; v0.w *= inv;
    v1.x *= inv; v1.y *= inv; v1.z *= inv; v1.w *= inv;
    ((float4*)prow)[tid]       = v0;
    ((float4*)prow)[tid + 256] = v1;
}

// ---------------------------------------------------------------------------
// Kernel 3: context = attn . K
// CTA tile 128(M) x 256(N), BK=16. A (attn) k-contiguous -> [row][k] SK;
// B (K matrix) d-contiguous -> [k][n] stride SN.
// smem floats: A0[2560] A1[2560] B0[16*SN] B1[16*SN]
// ---------------------------------------------------------------------------
__global__ __launch_bounds__(256, 1)
void k3_av(const float* __restrict__ A, const float* __restrict__ Kf,
           float* __restrict__ C)
{
    extern __shared__ unsigned sm[];
    unsigned* sA[2] = { sm,            sm + 128 * SK };
    unsigned* sB[2] = { sm + 2 * 128 * SK, sm + 2 * 128 * SK + 16 * SN };

    const int b  = blockIdx.z;
    const int m0 = blockIdx.y * 128;
    const int n0 = blockIdx.x * 256;

    const float* Ab = A  + (size_t)b * LQ_ * LK_;
    const float* Kb = Kf + (size_t)b * LK_ * HID_;

    const int tid  = threadIdx.x;
    const int wid  = tid >> 5;
    const int lane = tid & 31;
    const int qid  = lane >> 2;
    const int rid  = lane & 3;
    const int wm   = (wid & 1) * 64;
    const int wn   = (wid >> 1) * 64;

    // A loader: row = tid>>2 (+64), kq = (tid&3)*4
    const int lrow = tid >> 2;
    const int lkq  = (tid & 3) << 2;
    // B loader: kr = slot>>6, nc = (slot&63)*4
    const int lkr = tid >> 6;          // 0..3 (4 passes -> 0..15)
    const int lnc = (tid & 63) << 2;   // 0..252

    float acc[4][8][4];
#pragma unroll
    for (int i = 0; i < 4; i++)
#pragma unroll
        for (int j = 0; j < 8; j++)
#pragma unroll
            for (int c = 0; c < 4; c++) acc[i][j][c] = 0.0f;

    {
#pragma unroll
        for (int j = 0; j < 2; j++) {
            const int row = lrow + j * 64;
            float4 v = *(const float4*)(Ab + (size_t)(m0 + row) * LK_ + lkq);
            *(uint4*)&sA[0][row * SK + lkq] =
                make_uint4(f2tf(v.x), f2tf(v.y), f2tf(v.z), f2tf(v.w));
        }
#pragma unroll
        for (int j = 0; j < 4; j++) {
            const int kr = lkr + j * 4;
            float4 v = *(const float4*)(Kb + (size_t)kr * HID_ + n0 + lnc);
            *(uint4*)&sB[0][kr * SN + lnc] =
                make_uint4(f2tf(v.x), f2tf(v.y), f2tf(v.z), f2tf(v.w));
        }
    }

    const int NIT = LK_ / 16;
    for (int it = 0; it < NIT; it++) {
        __syncthreads();
        const int cur = it & 1;
        const bool more = (it + 1) < NIT;

        float4 pa[2], pb[4];
        if (more) {
            const int kk = (it + 1) * 16;
#pragma unroll
            for (int j = 0; j < 2; j++)
                pa[j] = *(const float4*)(Ab + (size_t)(m0 + lrow + j * 64) * LK_ + kk + lkq);
#pragma unroll
            for (int j = 0; j < 4; j++)
                pb[j] = *(const float4*)(Kb + (size_t)(kk + lkr + j * 4) * HID_ + n0 + lnc);
        }

#pragma unroll
        for (int ks = 0; ks < 16; ks += 8) {
            unsigned af[4][4];
#pragma unroll
            for (int mt = 0; mt < 4; mt++) {
                const int r = wm + mt * 16 + qid;
                af[mt][0] = sA[cur][r * SK + ks + rid];
                af[mt][1] = sA[cur][(r + 8) * SK + ks + rid];
                af[mt][2] = sA[cur][r * SK + ks + 4 + rid];
                af[mt][3] = sA[cur][(r + 8) * SK + ks + 4 + rid];
            }
            unsigned bf[8][2];
#pragma unroll
            for (int nt = 0; nt < 8; nt++) {
                const int c = wn + nt * 8 + qid;
                bf[nt][0] = sB[cur][(ks + rid) * SN + c];
                bf[nt][1] = sB[cur][(ks + 4 + rid) * SN + c];
            }
#pragma unroll
            for (int mt = 0; mt < 4; mt++)
#pragma unroll
                for (int nt = 0; nt < 8; nt++)
                    mma_tf32(acc[mt][nt], af[mt], bf[nt]);
        }

        if (more) {
            const int nxt = cur ^ 1;
#pragma unroll
            for (int j = 0; j < 2; j++) {
                const int row = lrow + j * 64;
                *(uint4*)&sA[nxt][row * SK + lkq] =
                    make_uint4(f2tf(pa[j].x), f2tf(pa[j].y), f2tf(pa[j].z), f2tf(pa[j].w));
            }
#pragma unroll
            for (int j = 0; j < 4; j++) {
                const int kr = lkr + j * 4;
                *(uint4*)&sB[nxt][kr * SN + lnc] =
                    make_uint4(f2tf(pb[j].x), f2tf(pb[j].y), f2tf(pb[j].z), f2tf(pb[j].w));
            }
        }
    }

#pragma unroll
    for (int mt = 0; mt < 4; mt++) {
#pragma unroll
        for (int nt = 0; nt < 8; nt++) {
            const int r = m0 + wm + mt * 16 + qid;
            const int c = n0 + wn + nt * 8 + 2 * rid;
            const size_t i0 = ((size_t)b * LQ_ + r) * HID_ + c;
            const size_t i1 = ((size_t)b * LQ_ + r + 8) * HID_ + c;
            *(float2*)(C + i0) = make_float2(acc[mt][nt][0], acc[mt][nt][1]);
            *(float2*)(C + i1) = make_float2(acc[mt][nt][2], acc[mt][nt][3]);
        }
    }
}

// ---------------------------------------------------------------------------
extern "C" void kernel_launch(void* const* d_in, const int* in_sizes, int n_in,
                              void* d_out, int out_size)
{
    const float* Q    = (const float*)d_in[0];
    const float* Kf   = (const float*)d_in[1];
    const float* mask = (const float*)d_in[2];

    float* ctx  = (float*)d_out;                      // [B, LQ, HID]
    float* attn = ctx + (size_t)B_ * LQ_ * HID_;      // [B, LQ, LK]

    const int smem1 = (2 * 128 * SK + 2 * 256 * SK) * 4;  // 61440 B
    const int smem3 = (2 * 128 * SK + 2 * 16 * SN) * 4;   // 54272 B

    static bool attr_set = false;
    if (!attr_set) {
        cudaFuncSetAttribute(k1_qk_exp, cudaFuncAttributeMaxDynamicSharedMemorySize, smem1);
        cudaFuncSetAttribute(k3_av,     cudaFuncAttributeMaxDynamicSharedMemorySize, smem3);
        attr_set = true;
    }

    dim3 g1(LK_ / 256, LQ_ / 128, B_);
    k1_qk_exp<<<g1, 256, smem1>>>(Q, Kf, mask, attn);

    k2_norm<<<B_ * LQ_, 256>>>(attn);

    dim3 g3(HID_ / 256, LQ_ / 128, B_);
    k3_av<<<g3, 256, smem3>>>(attn, Kf, ctx);
}

// round 5
// speedup vs baseline: 1.3250x; 1.3250x over previous
#include <cuda_runtime.h>
#include <math.h>
#include <stdint.h>

#define B_   8
#define LQ_  2048
#define LK_  2048
#define HID_ 1024

// smem strides (floats): k-major tiles [row][k] stride 20; n-major [k][n] stride 136.
#define SK 20
#define SN 136

__device__ __forceinline__ unsigned f2tf(float x) {
    unsigned u;
    asm("cvt.rna.tf32.f32 %0, %1;" : "=r"(u) : "f"(x));
    return u;
}

__device__ __forceinline__ void mma_tf32(float* d, const unsigned* a, const unsigned* b) {
    asm volatile(
        "mma.sync.aligned.m16n8k8.row.col.f32.tf32.tf32.f32 "
        "{%0,%1,%2,%3}, {%4,%5,%6,%7}, {%8,%9}, {%0,%1,%2,%3};\n"
        : "+f"(d[0]), "+f"(d[1]), "+f"(d[2]), "+f"(d[3])
        : "r"(a[0]), "r"(a[1]), "r"(a[2]), "r"(a[3]),
          "r"(b[0]), "r"(b[1]));
}

// ---------------------------------------------------------------------------
// Kernel 1: P = exp( (Q.K^T / 32) * mask )   (unnormalized; k2 normalizes)
// CTA tile 128(M) x 128(N), BK=16, 128 threads = 4 warps (2M x 2N),
// warp tile 64x64. Double-buffered dynamic smem (40KB) -> 2 CTAs/SM.
// ---------------------------------------------------------------------------
__global__ __launch_bounds__(128, 2)
void k1_qk_exp(const float* __restrict__ Q, const float* __restrict__ Kf,
               const float* __restrict__ mask, float* __restrict__ P)
{
    extern __shared__ unsigned sm[];
    // layout: A0[2560] A1[2560] B0[2560] B1[2560]
    unsigned* sA0 = sm;
    unsigned* sA1 = sm + 128 * SK;
    unsigned* sB0 = sm + 2 * 128 * SK;
    unsigned* sB1 = sm + 3 * 128 * SK;

    const int b  = blockIdx.z;
    const int m0 = blockIdx.y * 128;
    const int n0 = blockIdx.x * 128;

    const float* Qb = Q  + (size_t)b * LQ_ * HID_;
    const float* Kb = Kf + (size_t)b * LK_ * HID_;

    const int tid  = threadIdx.x;
    const int wid  = tid >> 5;
    const int lane = tid & 31;
    const int qid  = lane >> 2;        // 0..7
    const int rid  = lane & 3;         // 0..3
    const int wm   = (wid & 1) * 64;   // warp M offset
    const int wn   = (wid >> 1) * 64;  // warp N offset

    // loader: row = tid>>2 (+32j), kq = (tid&3)*4
    const int lrow = tid >> 2;          // 0..31
    const int lkq  = (tid & 3) << 2;    // 0,4,8,12

    float acc[4][8][4];
#pragma unroll
    for (int i = 0; i < 4; i++)
#pragma unroll
        for (int j = 0; j < 8; j++)
#pragma unroll
            for (int c = 0; c < 4; c++) acc[i][j][c] = 0.0f;

    // prologue: stage 0 into buffer 0
#pragma unroll
    for (int j = 0; j < 4; j++) {
        const int row = lrow + j * 32;
        float4 va = *(const float4*)(Qb + (size_t)(m0 + row) * HID_ + lkq);
        float4 vb = *(const float4*)(Kb + (size_t)(n0 + row) * HID_ + lkq);
        *(uint4*)&sA0[row * SK + lkq] =
            make_uint4(f2tf(va.x), f2tf(va.y), f2tf(va.z), f2tf(va.w));
        *(uint4*)&sB0[row * SK + lkq] =
            make_uint4(f2tf(vb.x), f2tf(vb.y), f2tf(vb.z), f2tf(vb.w));
    }

    const int NIT = HID_ / 16;
    for (int it = 0; it < NIT; it++) {
        __syncthreads();
        const unsigned* cA = (it & 1) ? sA1 : sA0;
        const unsigned* cB = (it & 1) ? sB1 : sB0;
        unsigned* nA = (it & 1) ? sA0 : sA1;
        unsigned* nB = (it & 1) ? sB0 : sB1;
        const bool more = (it + 1) < NIT;

        float4 pa[4], pb[4];
        if (more) {
            const int kk = (it + 1) * 16;
#pragma unroll
            for (int j = 0; j < 4; j++) {
                pa[j] = *(const float4*)(Qb + (size_t)(m0 + lrow + j * 32) * HID_ + kk + lkq);
                pb[j] = *(const float4*)(Kb + (size_t)(n0 + lrow + j * 32) * HID_ + kk + lkq);
            }
        }

#pragma unroll
        for (int ks = 0; ks < 16; ks += 8) {
            unsigned af[4][4];
#pragma unroll
            for (int mt = 0; mt < 4; mt++) {
                const int r = wm + mt * 16 + qid;
                af[mt][0] = cA[r * SK + ks + rid];
                af[mt][1] = cA[(r + 8) * SK + ks + rid];
                af[mt][2] = cA[r * SK + ks + 4 + rid];
                af[mt][3] = cA[(r + 8) * SK + ks + 4 + rid];
            }
            unsigned bf[8][2];
#pragma unroll
            for (int nt = 0; nt < 8; nt++) {
                const int c = wn + nt * 8 + qid;
                bf[nt][0] = cB[c * SK + ks + rid];
                bf[nt][1] = cB[c * SK + ks + 4 + rid];
            }
#pragma unroll
            for (int mt = 0; mt < 4; mt++)
#pragma unroll
                for (int nt = 0; nt < 8; nt++)
                    mma_tf32(acc[mt][nt], af[mt], bf[nt]);
        }

        if (more) {
#pragma unroll
            for (int j = 0; j < 4; j++) {
                const int row = lrow + j * 32;
                *(uint4*)&nA[row * SK + lkq] =
                    make_uint4(f2tf(pa[j].x), f2tf(pa[j].y), f2tf(pa[j].z), f2tf(pa[j].w));
                *(uint4*)&nB[row * SK + lkq] =
                    make_uint4(f2tf(pb[j].x), f2tf(pb[j].y), f2tf(pb[j].z), f2tf(pb[j].w));
            }
        }
    }

    // epilogue: scale, mask-multiply, exp, store
    const float s = 0.03125f;
#pragma unroll
    for (int mt = 0; mt < 4; mt++) {
#pragma unroll
        for (int nt = 0; nt < 8; nt++) {
            const int r = m0 + wm + mt * 16 + qid;
            const int c = n0 + wn + nt * 8 + 2 * rid;
            const size_t i0 = ((size_t)b * LQ_ + r) * LK_ + c;
            const size_t i1 = ((size_t)b * LQ_ + r + 8) * LK_ + c;
            float2 ma = *(const float2*)(mask + i0);
            float2 mb = *(const float2*)(mask + i1);
            float2 o0, o1;
            o0.x = __expf(acc[mt][nt][0] * s * ma.x);
            o0.y = __expf(acc[mt][nt][1] * s * ma.y);
            o1.x = __expf(acc[mt][nt][2] * s * mb.x);
            o1.y = __expf(acc[mt][nt][3] * s * mb.y);
            *(float2*)(P + i0) = o0;
            *(float2*)(P + i1) = o1;
        }
    }
}

// ---------------------------------------------------------------------------
// Kernel 2: per-row normalization
// ---------------------------------------------------------------------------
__global__ __launch_bounds__(256)
void k2_norm(float* __restrict__ P)
{
    __shared__ float red[256];
    float* prow = P + (size_t)blockIdx.x * LK_;
    const int tid = threadIdx.x;

    float4 v0 = ((const float4*)prow)[tid];
    float4 v1 = ((const float4*)prow)[tid + 256];
    float s = v0.x + v0.y + v0.z + v0.w + v1.x + v1.y + v1.z + v1.w;
    red[tid] = s;
    __syncthreads();
#pragma unroll
    for (int off = 128; off > 0; off >>= 1) {
        if (tid < off) red[tid] += red[tid + off];
        __syncthreads();
    }
    const float inv = 1.0f / red[0];
    v0.x *= inv; v0.y *= inv; v0.z *= inv; v0.w *= inv;
    v1.x *= inv; v1.y *= inv; v1.z *= inv; v1.w *= inv;
    ((float4*)prow)[tid]       = v0;
    ((float4*)prow)[tid + 256] = v1;
}

// ---------------------------------------------------------------------------
// Kernel 3: context = attn . K
// CTA tile 128(M) x 128(N), BK=16, 128 threads, warp tile 64x64.
// A (attn) [row][k] stride SK; B (K matrix) [k][n] stride SN.
// smem: A0 A1 (2560 each) + B0 B1 (16*SN each)
// ---------------------------------------------------------------------------
__global__ __launch_bounds__(128, 2)
void k3_av(const float* __restrict__ A, const float* __restrict__ Kf,
           float* __restrict__ C)
{
    extern __shared__ unsigned sm[];
    unsigned* sA0 = sm;
    unsigned* sA1 = sm + 128 * SK;
    unsigned* sB0 = sm + 2 * 128 * SK;
    unsigned* sB1 = sm + 2 * 128 * SK + 16 * SN;

    const int b  = blockIdx.z;
    const int m0 = blockIdx.y * 128;
    const int n0 = blockIdx.x * 128;

    const float* Ab = A  + (size_t)b * LQ_ * LK_;
    const float* Kb = Kf + (size_t)b * LK_ * HID_;

    const int tid  = threadIdx.x;
    const int wid  = tid >> 5;
    const int lane = tid & 31;
    const int qid  = lane >> 2;
    const int rid  = lane & 3;
    const int wm   = (wid & 1) * 64;
    const int wn   = (wid >> 1) * 64;

    // A loader: row = tid>>2 (+32j), kq = (tid&3)*4
    const int lrow = tid >> 2;
    const int lkq  = (tid & 3) << 2;
    // B loader: kr = tid>>5 (+4j), nc = (tid&31)*4
    const int lkr = tid >> 5;          // 0..3
    const int lnc = (tid & 31) << 2;   // 0..124

    float acc[4][8][4];
#pragma unroll
    for (int i = 0; i < 4; i++)
#pragma unroll
        for (int j = 0; j < 8; j++)
#pragma unroll
            for (int c = 0; c < 4; c++) acc[i][j][c] = 0.0f;

#pragma unroll
    for (int j = 0; j < 4; j++) {
        const int row = lrow + j * 32;
        float4 va = *(const float4*)(Ab + (size_t)(m0 + row) * LK_ + lkq);
        *(uint4*)&sA0[row * SK + lkq] =
            make_uint4(f2tf(va.x), f2tf(va.y), f2tf(va.z), f2tf(va.w));
        const int kr = lkr + j * 4;
        float4 vb = *(const float4*)(Kb + (size_t)kr * HID_ + n0 + lnc);
        *(uint4*)&sB0[kr * SN + lnc] =
            make_uint4(f2tf(vb.x), f2tf(vb.y), f2tf(vb.z), f2tf(vb.w));
    }

    const int NIT = LK_ / 16;
    for (int it = 0; it < NIT; it++) {
        __syncthreads();
        const unsigned* cA = (it & 1) ? sA1 : sA0;
        const unsigned* cB = (it & 1) ? sB1 : sB0;
        unsigned* nA = (it & 1) ? sA0 : sA1;
        unsigned* nB = (it & 1) ? sB0 : sB1;
        const bool more = (it + 1) < NIT;

        float4 pa[4], pb[4];
        if (more) {
            const int kk = (it + 1) * 16;
#pragma unroll
            for (int j = 0; j < 4; j++) {
                pa[j] = *(const float4*)(Ab + (size_t)(m0 + lrow + j * 32) * LK_ + kk + lkq);
                pb[j] = *(const float4*)(Kb + (size_t)(kk + lkr + j * 4) * HID_ + n0 + lnc);
            }
        }

#pragma unroll
        for (int ks = 0; ks < 16; ks += 8) {
            unsigned af[4][4];
#pragma unroll
            for (int mt = 0; mt < 4; mt++) {
                const int r = wm + mt * 16 + qid;
                af[mt][0] = cA[r * SK + ks + rid];
                af[mt][1] = cA[(r + 8) * SK + ks + rid];
                af[mt][2] = cA[r * SK + ks + 4 + rid];
                af[mt][3] = cA[(r + 8) * SK + ks + 4 + rid];
            }
            unsigned bf[8][2];
#pragma unroll
            for (int nt = 0; nt < 8; nt++) {
                const int c = wn + nt * 8 + qid;
                bf[nt][0] = cB[(ks + rid) * SN + c];
                bf[nt][1] = cB[(ks + 4 + rid) * SN + c];
            }
#pragma unroll
            for (int mt = 0; mt < 4; mt++)
#pragma unroll
                for (int nt = 0; nt < 8; nt++)
                    mma_tf32(acc[mt][nt], af[mt], bf[nt]);
        }

        if (more) {
#pragma unroll
            for (int j = 0; j < 4; j++) {
                const int row = lrow + j * 32;
                *(uint4*)&nA[row * SK + lkq] =
                    make_uint4(f2tf(pa[j].x), f2tf(pa[j].y), f2tf(pa[j].z), f2tf(pa[j].w));
                const int kr = lkr + j * 4;
                *(uint4*)&nB[kr * SN + lnc] =
                    make_uint4(f2tf(pb[j].x), f2tf(pb[j].y), f2tf(pb[j].z), f2tf(pb[j].w));
            }
        }
    }

#pragma unroll
    for (int mt = 0; mt < 4; mt++) {
#pragma unroll
        for (int nt = 0; nt < 8; nt++) {
            const int r = m0 + wm + mt * 16 + qid;
            const int c = n0 + wn + nt * 8 + 2 * rid;
            const size_t i0 = ((size_t)b * LQ_ + r) * HID_ + c;
            const size_t i1 = ((size_t)b * LQ_ + r + 8) * HID_ + c;
            *(float2*)(C + i0) = make_float2(acc[mt][nt][0], acc[mt][nt][1]);
            *(float2*)(C + i1) = make_float2(acc[mt][nt][2], acc[mt][nt][3]);
        }
    }
}

// ---------------------------------------------------------------------------
extern "C" void kernel_launch(void* const* d_in, const int* in_sizes, int n_in,
                              void* d_out, int out_size)
{
    const float* Q    = (const float*)d_in[0];
    const float* Kf   = (const float*)d_in[1];
    const float* mask = (const float*)d_in[2];

    float* ctx  = (float*)d_out;                      // [B, LQ, HID]
    float* attn = ctx + (size_t)B_ * LQ_ * HID_;      // [B, LQ, LK]

    const int smem1 = (4 * 128 * SK) * 4;                 // 40960 B
    const int smem3 = (2 * 128 * SK + 2 * 16 * SN) * 4;   // 37888 B

    static bool attr_set = false;
    if (!attr_set) {
        cudaFuncSetAttribute(k1_qk_exp, cudaFuncAttributeMaxDynamicSharedMemorySize, smem1);
        cudaFuncSetAttribute(k3_av,     cudaFuncAttributeMaxDynamicSharedMemorySize, smem3);
        attr_set = true;
    }

    dim3 g1(LK_ / 128, LQ_ / 128, B_);
    k1_qk_exp<<<g1, 128, smem1>>>(Q, Kf, mask, attn);

    k2_norm<<<B_ * LQ_, 256>>>(attn);

    dim3 g3(HID_ / 128, LQ_ / 128, B_);
    k3_av<<<g3, 128, smem3>>>(attn, Kf, ctx);
}

// round 6
// speedup vs baseline: 1.3264x; 1.0011x over previous
#include <cuda_runtime.h>
#include <math.h>
#include <stdint.h>

#define B_   8
#define LQ_  2048
#define LK_  2048
#define HID_ 1024

// smem strides (floats): k-major tiles [row][k] stride 20; n-major [k][n] stride 136.
#define SK 20
#define SN 136

__device__ __forceinline__ unsigned f2tf(float x) {
    unsigned u;
    asm("cvt.rna.tf32.f32 %0, %1;" : "=r"(u) : "f"(x));
    return u;
}

__device__ __forceinline__ void mma_tf32(float* d, const unsigned* a, const unsigned* b) {
    asm volatile(
        "mma.sync.aligned.m16n8k8.row.col.f32.tf32.tf32.f32 "
        "{%0,%1,%2,%3}, {%4,%5,%6,%7}, {%8,%9}, {%0,%1,%2,%3};\n"
        : "+f"(d[0]), "+f"(d[1]), "+f"(d[2]), "+f"(d[3])
        : "r"(a[0]), "r"(a[1]), "r"(a[2]), "r"(a[3]),
          "r"(b[0]), "r"(b[1]));
}

// ---------------------------------------------------------------------------
// Kernel 1: P = exp( (Q.K^T / 32) * mask )   (unnormalized; k2 normalizes)
// CTA tile 128(M) x 128(N), BK=16, 128 threads = 4 warps (2M x 2N),
// warp tile 64x64. Double-buffered dynamic smem (40KB) -> 2 CTAs/SM.
// ---------------------------------------------------------------------------
__global__ __launch_bounds__(128, 2)
void k1_qk_exp(const float* __restrict__ Q, const float* __restrict__ Kf,
               const float* __restrict__ mask, float* __restrict__ P)
{
    extern __shared__ unsigned sm[];
    // layout: A0[2560] A1[2560] B0[2560] B1[2560]
    unsigned* sA0 = sm;
    unsigned* sA1 = sm + 128 * SK;
    unsigned* sB0 = sm + 2 * 128 * SK;
    unsigned* sB1 = sm + 3 * 128 * SK;

    const int b  = blockIdx.z;
    const int m0 = blockIdx.y * 128;
    const int n0 = blockIdx.x * 128;

    const float* Qb = Q  + (size_t)b * LQ_ * HID_;
    const float* Kb = Kf + (size_t)b * LK_ * HID_;

    const int tid  = threadIdx.x;
    const int wid  = tid >> 5;
    const int lane = tid & 31;
    const int qid  = lane >> 2;        // 0..7
    const int rid  = lane & 3;         // 0..3
    const int wm   = (wid & 1) * 64;   // warp M offset
    const int wn   = (wid >> 1) * 64;  // warp N offset

    // loader: row = tid>>2 (+32j), kq = (tid&3)*4
    const int lrow = tid >> 2;          // 0..31
    const int lkq  = (tid & 3) << 2;    // 0,4,8,12

    float acc[4][8][4];
#pragma unroll
    for (int i = 0; i < 4; i++)
#pragma unroll
        for (int j = 0; j < 8; j++)
#pragma unroll
            for (int c = 0; c < 4; c++) acc[i][j][c] = 0.0f;

    // prologue: stage 0 into buffer 0
#pragma unroll
    for (int j = 0; j < 4; j++) {
        const int row = lrow + j * 32;
        float4 va = *(const float4*)(Qb + (size_t)(m0 + row) * HID_ + lkq);
        float4 vb = *(const float4*)(Kb + (size_t)(n0 + row) * HID_ + lkq);
        *(uint4*)&sA0[row * SK + lkq] =
            make_uint4(f2tf(va.x), f2tf(va.y), f2tf(va.z), f2tf(va.w));
        *(uint4*)&sB0[row * SK + lkq] =
            make_uint4(f2tf(vb.x), f2tf(vb.y), f2tf(vb.z), f2tf(vb.w));
    }

    const int NIT = HID_ / 16;
    for (int it = 0; it < NIT; it++) {
        __syncthreads();
        const unsigned* cA = (it & 1) ? sA1 : sA0;
        const unsigned* cB = (it & 1) ? sB1 : sB0;
        unsigned* nA = (it & 1) ? sA0 : sA1;
        unsigned* nB = (it & 1) ? sB0 : sB1;
        const bool more = (it + 1) < NIT;

        float4 pa[4], pb[4];
        if (more) {
            const int kk = (it + 1) * 16;
#pragma unroll
            for (int j = 0; j < 4; j++) {
                pa[j] = *(const float4*)(Qb + (size_t)(m0 + lrow + j * 32) * HID_ + kk + lkq);
                pb[j] = *(const float4*)(Kb + (size_t)(n0 + lrow + j * 32) * HID_ + kk + lkq);
            }
        }

#pragma unroll
        for (int ks = 0; ks < 16; ks += 8) {
            unsigned af[4][4];
#pragma unroll
            for (int mt = 0; mt < 4; mt++) {
                const int r = wm + mt * 16 + qid;
                af[mt][0] = cA[r * SK + ks + rid];
                af[mt][1] = cA[(r + 8) * SK + ks + rid];
                af[mt][2] = cA[r * SK + ks + 4 + rid];
                af[mt][3] = cA[(r + 8) * SK + ks + 4 + rid];
            }
            unsigned bf[8][2];
#pragma unroll
            for (int nt = 0; nt < 8; nt++) {
                const int c = wn + nt * 8 + qid;
                bf[nt][0] = cB[c * SK + ks + rid];
                bf[nt][1] = cB[c * SK + ks + 4 + rid];
            }
#pragma unroll
            for (int mt = 0; mt < 4; mt++)
#pragma unroll
                for (int nt = 0; nt < 8; nt++)
                    mma_tf32(acc[mt][nt], af[mt], bf[nt]);
        }

        if (more) {
#pragma unroll
            for (int j = 0; j < 4; j++) {
                const int row = lrow + j * 32;
                *(uint4*)&nA[row * SK + lkq] =
                    make_uint4(f2tf(pa[j].x), f2tf(pa[j].y), f2tf(pa[j].z), f2tf(pa[j].w));
                *(uint4*)&nB[row * SK + lkq] =
                    make_uint4(f2tf(pb[j].x), f2tf(pb[j].y), f2tf(pb[j].z), f2tf(pb[j].w));
            }
        }
    }

    // epilogue: scale, mask-multiply, exp, store
    const float s = 0.03125f;
#pragma unroll
    for (int mt = 0; mt < 4; mt++) {
#pragma unroll
        for (int nt = 0; nt < 8; nt++) {
            const int r = m0 + wm + mt * 16 + qid;
            const int c = n0 + wn + nt * 8 + 2 * rid;
            const size_t i0 = ((size_t)b * LQ_ + r) * LK_ + c;
            const size_t i1 = ((size_t)b * LQ_ + r + 8) * LK_ + c;
            float2 ma = *(const float2*)(mask + i0);
            float2 mb = *(const float2*)(mask + i1);
            float2 o0, o1;
            o0.x = __expf(acc[mt][nt][0] * s * ma.x);
            o0.y = __expf(acc[mt][nt][1] * s * ma.y);
            o1.x = __expf(acc[mt][nt][2] * s * mb.x);
            o1.y = __expf(acc[mt][nt][3] * s * mb.y);
            *(float2*)(P + i0) = o0;
            *(float2*)(P + i1) = o1;
        }
    }
}

// ---------------------------------------------------------------------------
// Kernel 2: per-row normalization
// ---------------------------------------------------------------------------
__global__ __launch_bounds__(256)
void k2_norm(float* __restrict__ P)
{
    __shared__ float red[256];
    float* prow = P + (size_t)blockIdx.x * LK_;
    const int tid = threadIdx.x;

    float4 v0 = ((const float4*)prow)[tid];
    float4 v1 = ((const float4*)prow)[tid + 256];
    float s = v0.x + v0.y + v0.z + v0.w + v1.x + v1.y + v1.z + v1.w;
    red[tid] = s;
    __syncthreads();
#pragma unroll
    for (int off = 128; off > 0; off >>= 1) {
        if (tid < off) red[tid] += red[tid + off];
        __syncthreads();
    }
    const float inv = 1.0f / red[0];
    v0.x *= inv; v0.y *= inv; v0.z *= inv; v0.w *= inv;
    v1.x *= inv; v1.y *= inv; v1.z *= inv; v1.w *= inv;
    ((float4*)prow)[tid]       = v0;
    ((float4*)prow)[tid + 256] = v1;
}

// ---------------------------------------------------------------------------
// Kernel 3: context = attn . K
// CTA tile 128(M) x 128(N), BK=16, 128 threads, warp tile 64x64.
// A (attn) [row][k] stride SK; B (K matrix) [k][n] stride SN.
// smem: A0 A1 (2560 each) + B0 B1 (16*SN each)
// ---------------------------------------------------------------------------
__global__ __launch_bounds__(128, 2)
void k3_av(const float* __restrict__ A, const float* __restrict__ Kf,
           float* __restrict__ C)
{
    extern __shared__ unsigned sm[];
    unsigned* sA0 = sm;
    unsigned* sA1 = sm + 128 * SK;
    unsigned* sB0 = sm + 2 * 128 * SK;
    unsigned* sB1 = sm + 2 * 128 * SK + 16 * SN;

    const int b  = blockIdx.z;
    const int m0 = blockIdx.y * 128;
    const int n0 = blockIdx.x * 128;

    const float* Ab = A  + (size_t)b * LQ_ * LK_;
    const float* Kb = Kf + (size_t)b * LK_ * HID_;

    const int tid  = threadIdx.x;
    const int wid  = tid >> 5;
    const int lane = tid & 31;
    const int qid  = lane >> 2;
    const int rid  = lane & 3;
    const int wm   = (wid & 1) * 64;
    const int wn   = (wid >> 1) * 64;

    // A loader: row = tid>>2 (+32j), kq = (tid&3)*4
    const int lrow = tid >> 2;
    const int lkq  = (tid & 3) << 2;
    // B loader: kr = tid>>5 (+4j), nc = (tid&31)*4
    const int lkr = tid >> 5;          // 0..3
    const int lnc = (tid & 31) << 2;   // 0..124

    float acc[4][8][4];
#pragma unroll
    for (int i = 0; i < 4; i++)
#pragma unroll
        for (int j = 0; j < 8; j++)
#pragma unroll
            for (int c = 0; c < 4; c++) acc[i][j][c] = 0.0f;

#pragma unroll
    for (int j = 0; j < 4; j++) {
        const int row = lrow + j * 32;
        float4 va = *(const float4*)(Ab + (size_t)(m0 + row) * LK_ + lkq);
        *(uint4*)&sA0[row * SK + lkq] =
            make_uint4(f2tf(va.x), f2tf(va.y), f2tf(va.z), f2tf(va.w));
        const int kr = lkr + j * 4;
        float4 vb = *(const float4*)(Kb + (size_t)kr * HID_ + n0 + lnc);
        *(uint4*)&sB0[kr * SN + lnc] =
            make_uint4(f2tf(vb.x), f2tf(vb.y), f2tf(vb.z), f2tf(vb.w));
    }

    const int NIT = LK_ / 16;
    for (int it = 0; it < NIT; it++) {
        __syncthreads();
        const unsigned* cA = (it & 1) ? sA1 : sA0;
        const unsigned* cB = (it & 1) ? sB1 : sB0;
        unsigned* nA = (it & 1) ? sA0 : sA1;
        unsigned* nB = (it & 1) ? sB0 : sB1;
        const bool more = (it + 1) < NIT;

        float4 pa[4], pb[4];
        if (more) {
            const int kk = (it + 1) * 16;
#pragma unroll
            for (int j = 0; j < 4; j++) {
                pa[j] = *(const float4*)(Ab + (size_t)(m0 + lrow + j * 32) * LK_ + kk + lkq);
                pb[j] = *(const float4*)(Kb + (size_t)(kk + lkr + j * 4) * HID_ + n0 + lnc);
            }
        }

#pragma unroll
        for (int ks = 0; ks < 16; ks += 8) {
            unsigned af[4][4];
#pragma unroll
            for (int mt = 0; mt < 4; mt++) {
                const int r = wm + mt * 16 + qid;
                af[mt][0] = cA[r * SK + ks + rid];
                af[mt][1] = cA[(r + 8) * SK + ks + rid];
                af[mt][2] = cA[r * SK + ks + 4 + rid];
                af[mt][3] = cA[(r + 8) * SK + ks + 4 + rid];
            }
            unsigned bf[8][2];
#pragma unroll
            for (int nt = 0; nt < 8; nt++) {
                const int c = wn + nt * 8 + qid;
                bf[nt][0] = cB[(ks + rid) * SN + c];
                bf[nt][1] = cB[(ks + 4 + rid) * SN + c];
            }
#pragma unroll
            for (int mt = 0; mt < 4; mt++)
#pragma unroll
                for (int nt = 0; nt < 8; nt++)
                    mma_tf32(acc[mt][nt], af[mt], bf[nt]);
        }

        if (more) {
#pragma unroll
            for (int j = 0; j < 4; j++) {
                const int row = lrow + j * 32;
                *(uint4*)&nA[row * SK + lkq] =
                    make_uint4(f2tf(pa[j].x), f2tf(pa[j].y), f2tf(pa[j].z), f2tf(pa[j].w));
                const int kr = lkr + j * 4;
                *(uint4*)&nB[kr * SN + lnc] =
                    make_uint4(f2tf(pb[j].x), f2tf(pb[j].y), f2tf(pb[j].z), f2tf(pb[j].w));
            }
        }
    }

#pragma unroll
    for (int mt = 0; mt < 4; mt++) {
#pragma unroll
        for (int nt = 0; nt < 8; nt++) {
            const int r = m0 + wm + mt * 16 + qid;
            const int c = n0 + wn + nt * 8 + 2 * rid;
            const size_t i0 = ((size_t)b * LQ_ + r) * HID_ + c;
            const size_t i1 = ((size_t)b * LQ_ + r + 8) * HID_ + c;
            *(float2*)(C + i0) = make_float2(acc[mt][nt][0], acc[mt][nt][1]);
            *(float2*)(C + i1) = make_float2(acc[mt][nt][2], acc[mt][nt][3]);
        }
    }
}

// ---------------------------------------------------------------------------
extern "C" void kernel_launch(void* const* d_in, const int* in_sizes, int n_in,
                              void* d_out, int out_size)
{
    const float* Q    = (const float*)d_in[0];
    const float* Kf   = (const float*)d_in[1];
    const float* mask = (const float*)d_in[2];

    float* ctx  = (float*)d_out;                      // [B, LQ, HID]
    float* attn = ctx + (size_t)B_ * LQ_ * HID_;      // [B, LQ, LK]

    const int smem1 = (4 * 128 * SK) * 4;                 // 40960 B
    const int smem3 = (2 * 128 * SK + 2 * 16 * SN) * 4;   // 37888 B

    static bool attr_set = false;
    if (!attr_set) {
        cudaFuncSetAttribute(k1_qk_exp, cudaFuncAttributeMaxDynamicSharedMemorySize, smem1);
        cudaFuncSetAttribute(k3_av,     cudaFuncAttributeMaxDynamicSharedMemorySize, smem3);
        attr_set = true;
    }

    dim3 g1(LK_ / 128, LQ_ / 128, B_);
    k1_qk_exp<<<g1, 128, smem1>>>(Q, Kf, mask, attn);

    k2_norm<<<B_ * LQ_, 256>>>(attn);

    dim3 g3(HID_ / 128, LQ_ / 128, B_);
    k3_av<<<g3, 128, smem3>>>(attn, Kf, ctx);
}